// round 1
// baseline (speedup 1.0000x reference)
#include <cuda_runtime.h>

#define NB 1024
#define NS 50
#define NH 64
#define NITEM 40000
#define TPB 256

__global__ __launch_bounds__(TPB, 2)
void rrd_kernel(const float* __restrict__ all_memory,
                const float* __restrict__ last_memory,
                const int*   __restrict__ seq_item,
                const float* __restrict__ Wr,
                const float* __restrict__ Ur,
                const float* __restrict__ Vr_w,
                float* __restrict__ out)
{
    __shared__ float xs[NS * NH];      // all_memory row   (12.8 KB)
    __shared__ float mat[NH * 65];     // padded Wr, then Ur (16.6 KB)
    __shared__ float lastm[NH];
    __shared__ float scores[64];
    __shared__ float probs[NS];

    const int tid = threadIdx.x;
    const int b   = blockIdx.x;
    const int k   = tid & 63;
    const int g   = tid >> 6;          // 0..3: s-group

    // ---- stage inputs into smem (coalesced) ----
    const float* am = all_memory + (size_t)b * (NS * NH);
    #pragma unroll
    for (int i = tid; i < NS * NH; i += TPB) xs[i] = am[i];
    if (tid < NH) lastm[tid] = last_memory[b * NH + tid];
    if (tid < 64) scores[tid] = 0.f;
    for (int i = tid; i < NH * NH; i += TPB) {
        int r = i >> 6, c = i & 63;
        mat[r * 65 + c] = Wr[i];       // pad-65: bank (k+h)%32 conflict-free
    }
    __syncthreads();

    // ---- l_k = sum_h last[h] * Wr[k,h] ----
    float lk = 0.f;
    #pragma unroll
    for (int h = 0; h < NH; h++) lk += lastm[h] * mat[k * 65 + h];
    __syncthreads();

    // ---- reload mat with Ur ----
    for (int i = tid; i < NH * NH; i += TPB) {
        int r = i >> 6, c = i & 63;
        mat[r * 65 + c] = Ur[i];
    }
    __syncthreads();

    // ---- Ur row k into registers ----
    float ur[NH];
    #pragma unroll
    for (int h = 0; h < NH; h++) ur[h] = mat[k * 65 + h];
    const float vk = Vr_w[k];

    // ---- scores: a[s,k] = x[s]·ur ; val = Vr_w[k]*tanh(a+l) ; reduce over k ----
    for (int s = g; s < NS; s += 4) {
        const float4* xr = reinterpret_cast<const float4*>(xs + s * NH);
        float acc = lk;
        #pragma unroll
        for (int i = 0; i < NH / 4; i++) {
            float4 v = xr[i];                      // broadcast LDS.128
            acc += v.x * ur[4*i]   + v.y * ur[4*i+1]
                 + v.z * ur[4*i+2] + v.w * ur[4*i+3];
        }
        float val = vk * tanhf(acc);
        #pragma unroll
        for (int o = 16; o; o >>= 1)
            val += __shfl_xor_sync(0xffffffffu, val, o);
        if ((tid & 31) == 0) atomicAdd(&scores[s], val);   // 2 partials/s
    }
    __syncthreads();

    // ---- softmax over S=50 (warp 0); Vr_b cancels under shift-invariance ----
    if (tid < 32) {
        float v0 = (tid      < NS) ? scores[tid]      : -1e30f;
        float v1 = (tid + 32 < NS) ? scores[tid + 32] : -1e30f;
        float m = fmaxf(v0, v1);
        #pragma unroll
        for (int o = 16; o; o >>= 1)
            m = fmaxf(m, __shfl_xor_sync(0xffffffffu, m, o));
        float e0 = (tid      < NS) ? __expf(v0 - m) : 0.f;
        float e1 = (tid + 32 < NS) ? __expf(v1 - m) : 0.f;
        float ssum = e0 + e1;
        #pragma unroll
        for (int o = 16; o; o >>= 1)
            ssum += __shfl_xor_sync(0xffffffffu, ssum, o);
        float inv = 1.f / ssum;
        if (tid      < NS) probs[tid]      = e0 * inv;
        if (tid + 32 < NS) probs[tid + 32] = e1 * inv;
    }

    // ---- zero the 40000-float output row (float4 stores) ----
    float* row = out + (size_t)b * NITEM;
    float4* row4 = reinterpret_cast<float4*>(row);
    const float4 z = make_float4(0.f, 0.f, 0.f, 0.f);
    for (int i = tid; i < NITEM / 4; i += TPB) row4[i] = z;
    __syncthreads();   // orders STG zeros before atomics; publishes probs

    // ---- scatter-add the 50 probs (atomics handle duplicate items) ----
    if (tid < NS) {
        int item = seq_item[b * NS + tid];
        atomicAdd(row + item, probs[tid]);
    }
}

extern "C" void kernel_launch(void* const* d_in, const int* in_sizes, int n_in,
                              void* d_out, int out_size)
{
    const float* all_memory  = (const float*)d_in[0];
    const float* last_memory = (const float*)d_in[1];
    const int*   seq_item    = (const int*)  d_in[2];
    const float* Wr          = (const float*)d_in[3];
    const float* Ur          = (const float*)d_in[4];
    const float* Vr_w        = (const float*)d_in[5];
    // d_in[6] = Vr_b (scalar) — softmax shift-invariant, unused.
    float* out = (float*)d_out;

    rrd_kernel<<<NB, TPB>>>(all_memory, last_memory, seq_item, Wr, Ur, Vr_w, out);
}